// round 3
// baseline (speedup 1.0000x reference)
#include <cuda_runtime.h>

#define TT 256

// Ping-pong scratch (static device arrays: no allocation anywhere).
// Max tensor: P8 = 4*32*32*32*256 = 33,554,432 floats.
__device__ float g_bufX[33554432];
__device__ float g_bufY[33554432];

// ---------------------------------------------------------------------------
// Dynamics kernel: per-neuron sequential loop over T.
// MODE 0: psp only                      (input layer)
// MODE 1: spike + psp                   (after conv)
// MODE 2: sumpool2 + spike + psp        (pool layers, gather fused)
// MODE 3: bilinear-up2 + spike + psp    (upsample layers, gather fused)
// MODE 4: spike only                    (final output)
// ---------------------------------------------------------------------------
template<int MODE>
__global__ __launch_bounds__(256)
void dyn_kernel(const float* __restrict__ in, float* __restrict__ out,
                int C, int H, int W, int N)
{
    int n = blockIdx.x * 256 + threadIdx.x;
    if (n >= N) return;

    const float dsr  = 0.9048374180359595f;   // exp(-1/10)
    const float psc  = 0.27182818284590452f;  // e/10
    const float dref = 0.36787944117144233f;  // exp(-1)

    const float *p0 = nullptr, *p1 = nullptr, *p2 = nullptr, *p3 = nullptr;
    float w00 = 0.f, w01 = 0.f, w10 = 0.f, w11 = 0.f;

    if (MODE == 2) {
        int x = n % W, y = (n / W) % H, bc = n / (W * H);
        int Win = 2 * W;
        const float* base = in + (((long)bc * (2 * H) + 2 * y) * Win + 2 * x) * TT;
        p0 = base;
        p1 = base + TT;
        p2 = base + (long)Win * TT;
        p3 = base + (long)(Win + 1) * TT;
    } else if (MODE == 3) {
        int x = n % W, y = (n / W) % H, bc = n / (W * H);
        int Hin = H / 2, Win = W / 2;
        int jy = y >> 1, jx = x >> 1;
        int ya, yb, xa, xb; float wya, wyb, wxa, wxb;
        if ((y & 1) == 0) { ya = (jy > 0) ? jy - 1 : 0; yb = jy; wya = 0.25f; wyb = 0.75f; }
        else              { ya = jy; yb = (jy + 1 < Hin) ? jy + 1 : Hin - 1; wya = 0.75f; wyb = 0.25f; }
        if ((x & 1) == 0) { xa = (jx > 0) ? jx - 1 : 0; xb = jx; wxa = 0.25f; wxb = 0.75f; }
        else              { xa = jx; xb = (jx + 1 < Win) ? jx + 1 : Win - 1; wxa = 0.75f; wxb = 0.25f; }
        const float* base = in + (long)bc * Hin * Win * TT;
        p0 = base + ((long)ya * Win + xa) * TT; w00 = wya * wxa;
        p1 = base + ((long)ya * Win + xb) * TT; w01 = wya * wxb;
        p2 = base + ((long)yb * Win + xa) * TT; w10 = wyb * wxa;
        p3 = base + ((long)yb * Win + xb) * TT; w11 = wyb * wxb;
    } else {
        p0 = in + (long)n * TT;
    }

    float* ob = out + (long)n * TT;

    float g1 = 0.f, g2 = 0.f, r = 0.f;
    for (int t = 0; t < TT; t += 4) {
        float u[4];
        if (MODE == 2) {
            float4 a = *(const float4*)(p0 + t);
            float4 b = *(const float4*)(p1 + t);
            float4 c = *(const float4*)(p2 + t);
            float4 d = *(const float4*)(p3 + t);
            u[0] = 2.75f * ((a.x + b.x) + (c.x + d.x));
            u[1] = 2.75f * ((a.y + b.y) + (c.y + d.y));
            u[2] = 2.75f * ((a.z + b.z) + (c.z + d.z));
            u[3] = 2.75f * ((a.w + b.w) + (c.w + d.w));
        } else if (MODE == 3) {
            float4 a = *(const float4*)(p0 + t);
            float4 b = *(const float4*)(p1 + t);
            float4 c = *(const float4*)(p2 + t);
            float4 d = *(const float4*)(p3 + t);
            u[0] = w00 * a.x + w01 * b.x + w10 * c.x + w11 * d.x;
            u[1] = w00 * a.y + w01 * b.y + w10 * c.y + w11 * d.y;
            u[2] = w00 * a.z + w01 * b.z + w10 * c.z + w11 * d.z;
            u[3] = w00 * a.w + w01 * b.w + w10 * c.w + w11 * d.w;
        } else {
            float4 a = *(const float4*)(p0 + t);
            u[0] = a.x; u[1] = a.y; u[2] = a.z; u[3] = a.w;
        }

        float o[4];
        #pragma unroll
        for (int j = 0; j < 4; j++) {
            if (MODE == 0) {
                g1 = fmaf(dsr, g1, u[j]);
                g2 = fmaf(dsr, g2, g1);
                o[j] = psc * (g2 - g1);
            } else {
                float v = u[j] + r - 10.0f;
                float s = (v >= 0.f) ? 1.f : 0.f;
                r = dref * (r - 20.f * s);
                if (MODE == 4) {
                    o[j] = s;
                } else {
                    g1 = fmaf(dsr, g1, s);
                    g2 = fmaf(dsr, g2, g1);
                    o[j] = psc * (g2 - g1);
                }
            }
        }
        *(float4*)(ob + t) = make_float4(o[0], o[1], o[2], o[3]);
    }
}

// ---------------------------------------------------------------------------
// T-vectorized conv: one output pixel per block, OCG output channels,
// 128 threads x 2 timesteps each (float2). Weights staged to smem in
// [ic*KS*KS + k][oc] order so the inner loop does float4 weight loads.
// ---------------------------------------------------------------------------
template<int IC, int KS, int PAD, int OCG>
__global__ __launch_bounds__(128)
void conv_kernel(const float* __restrict__ in, const float* __restrict__ wgt,
                 float* __restrict__ out, int H, int W, int OC)
{
    __shared__ float sw[IC * KS * KS * OCG];

    int pix = blockIdx.x;
    int x = pix % W, y = (pix / W) % H, b = pix / (W * H);
    int oc0 = blockIdx.y * OCG;

    for (int i = threadIdx.x; i < IC * KS * KS * OCG; i += 128) {
        int k = i / OCG, o = i % OCG;
        sw[i] = wgt[(long)(oc0 + o) * IC * KS * KS + k];
    }
    __syncthreads();

    int t = threadIdx.x * 2;
    float2 acc[OCG];
    #pragma unroll
    for (int o = 0; o < OCG; o++) acc[o] = make_float2(0.f, 0.f);

    const long planeT = (long)H * W * TT;
    const float* inb = in + (long)b * IC * planeT + t;

    #pragma unroll
    for (int kh = 0; kh < KS; kh++) {
        int yy = y + kh - PAD;
        if (yy < 0 || yy >= H) continue;
        #pragma unroll
        for (int kw = 0; kw < KS; kw++) {
            int xx = x + kw - PAD;
            if (xx < 0 || xx >= W) continue;
            const float* p = inb + ((long)yy * W + xx) * TT;
            int kidx = kh * KS + kw;
            #pragma unroll 4
            for (int ic = 0; ic < IC; ic++) {
                float2 v = *(const float2*)(p + (long)ic * planeT);
                const float* swp = &sw[(ic * KS * KS + kidx) * OCG];
                if constexpr (OCG % 4 == 0) {
                    #pragma unroll
                    for (int o = 0; o < OCG; o += 4) {
                        float4 wv = *(const float4*)(swp + o);
                        acc[o    ].x = fmaf(wv.x, v.x, acc[o    ].x);
                        acc[o    ].y = fmaf(wv.x, v.y, acc[o    ].y);
                        acc[o + 1].x = fmaf(wv.y, v.x, acc[o + 1].x);
                        acc[o + 1].y = fmaf(wv.y, v.y, acc[o + 1].y);
                        acc[o + 2].x = fmaf(wv.z, v.x, acc[o + 2].x);
                        acc[o + 2].y = fmaf(wv.z, v.y, acc[o + 2].y);
                        acc[o + 3].x = fmaf(wv.w, v.x, acc[o + 3].x);
                        acc[o + 3].y = fmaf(wv.w, v.y, acc[o + 3].y);
                    }
                } else {
                    #pragma unroll
                    for (int o = 0; o < OCG; o++) {
                        float wv = swp[o];
                        acc[o].x = fmaf(wv, v.x, acc[o].x);
                        acc[o].y = fmaf(wv, v.y, acc[o].y);
                    }
                }
            }
        }
    }

    float* ob = out + ((long)b * OC + oc0) * planeT + ((long)y * W + x) * TT + t;
    #pragma unroll
    for (int o = 0; o < OCG; o++)
        *(float2*)(ob + (long)o * planeT) = acc[o];
}

// ---------------------------------------------------------------------------
// Launch sequence (15 kernels, ping-pong X<->Y):
//   P0=psp(in); A1=conv1(P0); P1=sp(A1); P2=pool_sp(P1); A3=conv2(P2);
//   P3=sp(A3); P4=pool_sp(P3); A5=conv3(P4); P5=sp(A5); P6=up_sp(P5);
//   A7=conv4(P6); P7=sp(A7); P8=up_sp(P7); A9=conv_out(P8); out=spike(A9)
// ---------------------------------------------------------------------------
extern "C" void kernel_launch(void* const* d_in, const int* in_sizes, int n_in,
                              void* d_out, int out_size)
{
    const float* inp = (const float*)d_in[0];  // [4,1,32,32,256]
    const float* w1  = (const float*)d_in[1];  // [16,1,5,5,1]
    const float* w2  = (const float*)d_in[2];  // [32,16,3,3,1]
    const float* w3  = (const float*)d_in[3];  // [64,32,3,3,1]
    const float* w4  = (const float*)d_in[4];  // [32,64,3,3,1]
    const float* wo  = (const float*)d_in[5];  // [1,32,1,1,1]
    float* out = (float*)d_out;

    float *X, *Y;
    cudaGetSymbolAddress((void**)&X, g_bufX);
    cudaGetSymbolAddress((void**)&Y, g_bufY);

    #define DYNG(N) dim3(((N) + 255) / 256)

    // L1: psp(input) -> X ; conv1 -> Y ; spike+psp -> X
    dyn_kernel<0><<<DYNG(4096), 256>>>(inp, X, 1, 32, 32, 4096);
    conv_kernel<1, 5, 2, 16><<<dim3(4096, 1), 128>>>(X, w1, Y, 32, 32, 16);
    dyn_kernel<1><<<DYNG(65536), 256>>>(Y, X, 16, 32, 32, 65536);

    // L2: pool + spike + psp -> Y   (P2: [4,16,16,16])
    dyn_kernel<2><<<DYNG(16384), 256>>>(X, Y, 16, 16, 16, 16384);

    // L3: conv2 -> X ; spike+psp -> Y
    conv_kernel<16, 3, 1, 16><<<dim3(1024, 2), 128>>>(Y, w2, X, 16, 16, 32);
    dyn_kernel<1><<<DYNG(32768), 256>>>(X, Y, 32, 16, 16, 32768);

    // L4: pool + spike + psp -> X   (P4: [4,32,8,8])
    dyn_kernel<2><<<DYNG(8192), 256>>>(Y, X, 32, 8, 8, 8192);

    // L5: conv3 -> Y ; spike+psp -> X
    conv_kernel<32, 3, 1, 16><<<dim3(256, 4), 128>>>(X, w3, Y, 8, 8, 64);
    dyn_kernel<1><<<DYNG(16384), 256>>>(Y, X, 64, 8, 8, 16384);

    // L6: upsample + spike + psp -> Y   (P6: [4,64,16,16])
    dyn_kernel<3><<<DYNG(65536), 256>>>(X, Y, 64, 16, 16, 65536);

    // L7: conv4 -> X ; spike+psp -> Y
    conv_kernel<64, 3, 1, 16><<<dim3(1024, 2), 128>>>(Y, w4, X, 16, 16, 32);
    dyn_kernel<1><<<DYNG(32768), 256>>>(X, Y, 32, 16, 16, 32768);

    // L8: upsample + spike + psp -> X   (P8: [4,32,32,32])
    dyn_kernel<3><<<DYNG(131072), 256>>>(Y, X, 32, 32, 32, 131072);

    // L9: 1x1 conv -> Y ; spike only -> d_out
    conv_kernel<32, 1, 0, 1><<<dim3(4096, 1), 128>>>(X, wo, Y, 32, 32, 1);
    dyn_kernel<4><<<DYNG(4096), 256>>>(Y, out, 1, 32, 32, 4096);

    #undef DYNG
}